// round 10
// baseline (speedup 1.0000x reference)
#include <cuda_runtime.h>
#include <cuda_bf16.h>
#include <cstdint>

#define NROWS  32768
#define KCODES 1024
#define DIM    256
#define QELEMS (NROWS * DIM)
#define MARGIN 6.0e-3f
#define CAP    32

// Screen smem layout (bytes): A/B double buffers 8KB each
#define S_A0    0
#define S_A1    8192
#define S_B0    16384
#define S_B1    24576
#define S_SE    32768       // 1024 floats
#define S_RMIN  36864       // 128 u32
#define S_CCNT  37376       // 128 int
#define S_CIDX  37888       // 128*32 int = 16KB
#define S_TOTAL 54272

// ---- scratch (static device globals) ----
__device__ int      g_idx[NROWS];
__device__ float    g_se[KCODES];
__device__ float    g_szi[NROWS];
__device__ int      g_counts[KCODES];
__device__ double   g_ssd;
__device__ uint32_t g_af[QELEMS / 2];        // bf16-packed A fragments (16MB)
__device__ uint32_t g_bf[KCODES * DIM / 2];  // bf16-packed B fragments (512KB)
__device__ int      g_ccnt[NROWS];
__device__ int      g_cidx[(size_t)NROWS * CAP];

__device__ __forceinline__ uint32_t smem_u32(const void* p) {
    uint32_t a;
    asm("{ .reg .u64 t; cvta.to.shared.u64 t, %1; cvt.u32.u64 %0, t; }"
        : "=r"(a) : "l"(p));
    return a;
}
__device__ __forceinline__ uint32_t pack_bf2(float lo, float hi) {
    uint32_t l = __bfloat16_as_ushort(__float2bfloat16(lo));
    uint32_t h = __bfloat16_as_ushort(__float2bfloat16(hi));
    return l | (h << 16);
}
__device__ __forceinline__ void cp16(uint32_t s, const void* g) {
    asm volatile("cp.async.cg.shared.global [%0], [%1], 16;" :: "r"(s), "l"(g));
}
#define CP_COMMIT() asm volatile("cp.async.commit_group;" ::: "memory")
#define CP_WAIT1()  asm volatile("cp.async.wait_group 1;" ::: "memory")
#define CP_WAIT0()  asm volatile("cp.async.wait_group 0;" ::: "memory")

// bf16 m16n8k16 MMA, fp32 accum (fragment maps validated in R8)
__device__ __forceinline__ void mma_bf16(float* c, const uint4& a, const uint2& b) {
    asm volatile(
        "mma.sync.aligned.m16n8k16.row.col.f32.bf16.bf16.f32 "
        "{%0,%1,%2,%3}, {%4,%5,%6,%7}, {%8,%9}, {%0,%1,%2,%3};"
        : "+f"(c[0]), "+f"(c[1]), "+f"(c[2]), "+f"(c[3])
        : "r"(a.x), "r"(a.y), "r"(a.z), "r"(a.w), "r"(b.x), "r"(b.y));
}

// ---- reference-exact sequential fp32 sumsq (DO NOT CHANGE ORDER) ----
__global__ void rowsq_kernel(const float* __restrict__ x) {
    int row = blockIdx.x * blockDim.x + threadIdx.x;
    if (row >= NROWS) return;
    const float4* p = reinterpret_cast<const float4*>(x) + (size_t)row * (DIM / 4);
    float s = 0.0f;
    #pragma unroll 4
    for (int i = 0; i < DIM / 4; i++) {
        float4 v = __ldg(p + i);
        s = __fadd_rn(s, __fmul_rn(v.x, v.x));
        s = __fadd_rn(s, __fmul_rn(v.y, v.y));
        s = __fadd_rn(s, __fmul_rn(v.z, v.z));
        s = __fadd_rn(s, __fmul_rn(v.w, v.w));
    }
    g_szi[row] = s;
}
__global__ void codesq_zero_kernel(const float* __restrict__ cb) {
    int code = blockIdx.x * blockDim.x + threadIdx.x;
    g_counts[code] = 0;
    if (code == 0) g_ssd = 0.0;
    const float4* p = reinterpret_cast<const float4*>(cb) + (size_t)code * (DIM / 4);
    float s = 0.0f;
    #pragma unroll 4
    for (int i = 0; i < DIM / 4; i++) {
        float4 v = __ldg(p + i);
        s = __fadd_rn(s, __fmul_rn(v.x, v.x));
        s = __fadd_rn(s, __fmul_rn(v.y, v.y));
        s = __fadd_rn(s, __fmul_rn(v.z, v.z));
        s = __fadd_rn(s, __fmul_rn(v.w, v.w));
    }
    g_se[code] = s;
}

// ---- pack A bf16 fragments: [mb(256)][kc(8)][ks2(2)][mt(8)][lane(32)] uint4 ----
// a0:(r,k..k+1) a1:(r+8,k..k+1) a2:(r,k+8..k+9) a3:(r+8,k+8..k+9)
__global__ void packA_kernel(const float* __restrict__ x) {
    int t = blockIdx.x * 256 + threadIdx.x;          // 0 .. 2^20-1
    int lane = t & 31, mt = (t >> 5) & 7, ks2 = (t >> 8) & 1;
    int kc = (t >> 9) & 7, mb = t >> 12;
    int row = mb * 128 + mt * 16 + (lane >> 2);
    int k0 = kc * 32 + ks2 * 16 + (lane & 3) * 2;
    const float2* x2 = reinterpret_cast<const float2*>(x);
    float2 v0 = x2[((size_t)row * DIM + k0) >> 1];
    float2 v1 = x2[((size_t)(row + 8) * DIM + k0) >> 1];
    float2 v2 = x2[((size_t)row * DIM + k0 + 8) >> 1];
    float2 v3 = x2[((size_t)(row + 8) * DIM + k0 + 8) >> 1];
    uint4 o;
    o.x = pack_bf2(v0.x, v0.y);
    o.y = pack_bf2(v1.x, v1.y);
    o.z = pack_bf2(v2.x, v2.y);
    o.w = pack_bf2(v3.x, v3.y);
    reinterpret_cast<uint4*>(g_af)[t] = o;
}
// ---- pack B bf16 fragments: [nb(8)][kc(8)][ks2(2)][nt(16)][lane(32)] uint2 ----
__global__ void packB_kernel(const float* __restrict__ cb) {
    int t = blockIdx.x * 256 + threadIdx.x;          // 0 .. 65535
    int lane = t & 31, nt = (t >> 5) & 15, ks2 = (t >> 9) & 1;
    int kc = (t >> 10) & 7, nb = t >> 13;
    int n = nb * 128 + nt * 8 + (lane >> 2);
    int k0 = kc * 32 + ks2 * 16 + (lane & 3) * 2;
    const float2* c2 = reinterpret_cast<const float2*>(cb);
    float2 w0 = c2[((size_t)n * DIM + k0) >> 1];
    float2 w1 = c2[((size_t)n * DIM + k0 + 8) >> 1];
    uint2 o;
    o.x = pack_bf2(w0.x, w0.y);
    o.y = pack_bf2(w1.x, w1.y);
    reinterpret_cast<uint2*>(g_bf)[t] = o;
}

// ---- bf16 screening GEMM + fused candidate selection (R7 shape, occ 2) ----
__global__ __launch_bounds__(256, 2)
void gemm_screen_kernel() {
    extern __shared__ char sm[];
    const uint32_t sb = smem_u32(sm);
    const int tid = threadIdx.x;
    const int w = tid >> 5, lane = tid & 31;
    const int wm = w & 3, wn = w >> 2;        // 4 M-subtiles x 2 N-subtiles
    const int g = lane >> 2, tig = lane & 3;
    const int rowBase = blockIdx.x * 128;

    float* se_sm = reinterpret_cast<float*>(sm + S_SE);
    uint32_t* rmin = reinterpret_cast<uint32_t*>(sm + S_RMIN);
    int* ccnt = reinterpret_cast<int*>(sm + S_CCNT);
    int* cidx = reinterpret_cast<int*>(sm + S_CIDX);

    #pragma unroll
    for (int i = 0; i < 4; i++) se_sm[i * 256 + tid] = g_se[i * 256 + tid];
    if (tid < 128) { rmin[tid] = 0x7F800000u; ccnt[tid] = 0; }

    float szi[4];
    #pragma unroll
    for (int mt_i = 0; mt_i < 2; mt_i++)
        #pragma unroll
        for (int h = 0; h < 2; h++)
            szi[mt_i * 2 + h] = g_szi[rowBase + wm * 32 + mt_i * 16 + h * 8 + g];
    __syncthreads();

    const uint4* af4 = reinterpret_cast<const uint4*>(g_af);

    float C[2][8][4];

    {   // stage s=0: A kc0 (8KB) + B nb0/kc0 (8KB)
        const uint4* asrc = af4 + (size_t)blockIdx.x * 4096;
        const char* bsrc = reinterpret_cast<const char*>(g_bf);
        #pragma unroll
        for (int i = 0; i < 2; i++) {
            int idx = i * 256 + tid;
            cp16(sb + S_A0 + idx * 16, asrc + idx);
            cp16(sb + S_B0 + idx * 16, bsrc + idx * 16);
        }
        CP_COMMIT();
    }

    #pragma unroll 1
    for (int s = 0; s < 64; s++) {
        const int nb = s >> 3, kc = s & 7, buf = s & 1;

        if (s < 63) {
            int kc2 = (s + 1) & 7;
            const uint4* asrc = af4 + ((size_t)blockIdx.x * 8 + kc2) * 512;
            const char* bsrc = reinterpret_cast<const char*>(g_bf) + (size_t)(s + 1) * 8192;
            uint32_t abase = sb + ((s + 1) & 1 ? S_A1 : S_A0);
            uint32_t bbase = sb + ((s + 1) & 1 ? S_B1 : S_B0);
            #pragma unroll
            for (int i = 0; i < 2; i++) {
                int idx = i * 256 + tid;
                cp16(abase + idx * 16, asrc + idx);
                cp16(bbase + idx * 16, bsrc + idx * 16);
            }
            CP_COMMIT();
            CP_WAIT1();
        } else {
            CP_WAIT0();
        }
        __syncthreads();

        if (kc == 0) {
            #pragma unroll
            for (int m = 0; m < 2; m++)
                #pragma unroll
                for (int j = 0; j < 8; j++)
                    #pragma unroll
                    for (int q = 0; q < 4; q++) C[m][j][q] = 0.0f;
        }

        const char* Ab = sm + (buf ? S_A1 : S_A0);
        const char* Bb = sm + (buf ? S_B1 : S_B0);
        #pragma unroll
        for (int ks2 = 0; ks2 < 2; ks2++) {
            uint4 A0 = *reinterpret_cast<const uint4*>(
                Ab + ((ks2 * 8 + wm * 2 + 0) * 32 + lane) * 16);
            uint4 A1 = *reinterpret_cast<const uint4*>(
                Ab + ((ks2 * 8 + wm * 2 + 1) * 32 + lane) * 16);
            #pragma unroll
            for (int j = 0; j < 8; j++) {
                uint2 b = *reinterpret_cast<const uint2*>(
                    Bb + ((ks2 * 16 + wn * 8 + j) * 32 + lane) * 8);
                mma_bf16(C[0][j], A0, b);
                mma_bf16(C[1][j], A1, b);
            }
        }
        __syncthreads();

        if (kc == 7) {
            // epilogue: candidate = d <= min(cached_row_min, local_min) + MARGIN
            #pragma unroll
            for (int mt_i = 0; mt_i < 2; mt_i++) {
                int rl0 = wm * 32 + mt_i * 16 + g;
                int rl1 = rl0 + 8;
                float s0 = szi[mt_i * 2], s1 = szi[mt_i * 2 + 1];
                float d0v[16], d1v[16];
                float lm0 = 3.0e38f, lm1 = 3.0e38f;
                #pragma unroll
                for (int j = 0; j < 8; j++) {
                    int colb = nb * 128 + wn * 64 + j * 8 + tig * 2;
                    float se0 = se_sm[colb], se1 = se_sm[colb + 1];
                    d0v[j * 2]     = fmaf(-2.0f, C[mt_i][j][0], s0 + se0);
                    d0v[j * 2 + 1] = fmaf(-2.0f, C[mt_i][j][1], s0 + se1);
                    d1v[j * 2]     = fmaf(-2.0f, C[mt_i][j][2], s1 + se0);
                    d1v[j * 2 + 1] = fmaf(-2.0f, C[mt_i][j][3], s1 + se1);
                    lm0 = fminf(lm0, fminf(d0v[j * 2], d0v[j * 2 + 1]));
                    lm1 = fminf(lm1, fminf(d1v[j * 2], d1v[j * 2 + 1]));
                }
                float cm0 = fminf(__uint_as_float(rmin[rl0]), lm0);
                float cm1 = fminf(__uint_as_float(rmin[rl1]), lm1);
                atomicMin(&rmin[rl0], __float_as_uint(lm0));
                atomicMin(&rmin[rl1], __float_as_uint(lm1));
                float t0 = cm0 + MARGIN, t1 = cm1 + MARGIN;
                #pragma unroll
                for (int q = 0; q < 16; q++) {
                    int code = nb * 128 + wn * 64 + (q >> 1) * 8 + tig * 2 + (q & 1);
                    if (d0v[q] <= t0) {
                        int p = atomicAdd(&ccnt[rl0], 1);
                        if (p < CAP) cidx[rl0 * CAP + p] = code;
                    }
                    if (d1v[q] <= t1) {
                        int p = atomicAdd(&ccnt[rl1], 1);
                        if (p < CAP) cidx[rl1 * CAP + p] = code;
                    }
                }
            }
        }
    }

    __syncthreads();
    if (tid < 128) g_ccnt[rowBase + tid] = ccnt[tid];
    #pragma unroll
    for (int i = 0; i < 16; i++) {
        int li = i * 256 + tid;                 // 0..4095
        int r = li >> 5, k = li & 31;
        if (k < ccnt[r])
            g_cidx[(size_t)(rowBase + r) * CAP + k] = cidx[r * CAP + k];
    }
}

// ---- fused refine (exact argmin over candidates) + gather/output/ssd/hist ----
__global__ void refine_gather_kernel(const float* __restrict__ x,
                                     const float* __restrict__ cb,
                                     float* __restrict__ out) {
    __shared__ double warpsum[8];
    int w = threadIdx.x >> 5, lane = threadIdx.x & 31;
    int row = blockIdx.x * 8 + w;

    float4 xa = *reinterpret_cast<const float4*>(x + (size_t)row * DIM + lane * 8);
    float4 xb = *reinterpret_cast<const float4*>(x + (size_t)row * DIM + lane * 8 + 4);
    float szi = g_szi[row];
    int cnt = g_ccnt[row];

    float bd = 3.0e38f;
    int bi = 0x7FFFFFFF;
    if (cnt <= CAP) {
        for (int k = 0; k < cnt; k++) {
            int c = g_cidx[(size_t)row * CAP + k];
            float4 ea = *reinterpret_cast<const float4*>(cb + (size_t)c * DIM + lane * 8);
            float4 eb = *reinterpret_cast<const float4*>(cb + (size_t)c * DIM + lane * 8 + 4);
            float p = xa.x * ea.x;
            p = fmaf(xa.y, ea.y, p); p = fmaf(xa.z, ea.z, p); p = fmaf(xa.w, ea.w, p);
            p = fmaf(xb.x, eb.x, p); p = fmaf(xb.y, eb.y, p);
            p = fmaf(xb.z, eb.z, p); p = fmaf(xb.w, eb.w, p);
            #pragma unroll
            for (int off = 16; off > 0; off >>= 1) p += __shfl_xor_sync(0xffffffffu, p, off);
            // reference-exact epilogue: dist = fl(fl(szi+se) - fl(2*dot))
            float dist = __fsub_rn(__fadd_rn(szi, g_se[c]), __fmul_rn(2.0f, p));
            if (dist < bd || (dist == bd && c < bi)) { bd = dist; bi = c; }
        }
    } else {
        // overflow fallback: exact scan of all codes (expected never)
        for (int c = 0; c < KCODES; c++) {
            float4 ea = *reinterpret_cast<const float4*>(cb + (size_t)c * DIM + lane * 8);
            float4 eb = *reinterpret_cast<const float4*>(cb + (size_t)c * DIM + lane * 8 + 4);
            float p = xa.x * ea.x;
            p = fmaf(xa.y, ea.y, p); p = fmaf(xa.z, ea.z, p); p = fmaf(xa.w, ea.w, p);
            p = fmaf(xb.x, eb.x, p); p = fmaf(xb.y, eb.y, p);
            p = fmaf(xb.z, eb.z, p); p = fmaf(xb.w, eb.w, p);
            #pragma unroll
            for (int off = 16; off > 0; off >>= 1) p += __shfl_xor_sync(0xffffffffu, p, off);
            float dist = __fsub_rn(__fadd_rn(szi, g_se[c]), __fmul_rn(2.0f, p));
            if (dist < bd) { bd = dist; bi = c; }   // ascending: '<' keeps lowest
        }
    }

    if (lane == 0) { g_idx[row] = bi; atomicAdd(&g_counts[bi], 1); }

    // gather + straight-through output + ssd (reference rounding: o = x + (q-x))
    float4 qa = *reinterpret_cast<const float4*>(cb + (size_t)bi * DIM + lane * 8);
    float4 qb = *reinterpret_cast<const float4*>(cb + (size_t)bi * DIM + lane * 8 + 4);
    float4 da, db, oa, ob;
    da.x = __fsub_rn(qa.x, xa.x); da.y = __fsub_rn(qa.y, xa.y);
    da.z = __fsub_rn(qa.z, xa.z); da.w = __fsub_rn(qa.w, xa.w);
    db.x = __fsub_rn(qb.x, xb.x); db.y = __fsub_rn(qb.y, xb.y);
    db.z = __fsub_rn(qb.z, xb.z); db.w = __fsub_rn(qb.w, xb.w);
    oa.x = __fadd_rn(xa.x, da.x); oa.y = __fadd_rn(xa.y, da.y);
    oa.z = __fadd_rn(xa.z, da.z); oa.w = __fadd_rn(xa.w, da.w);
    ob.x = __fadd_rn(xb.x, db.x); ob.y = __fadd_rn(xb.y, db.y);
    ob.z = __fadd_rn(xb.z, db.z); ob.w = __fadd_rn(xb.w, db.w);
    *reinterpret_cast<float4*>(out + (size_t)row * DIM + lane * 8)     = oa;
    *reinterpret_cast<float4*>(out + (size_t)row * DIM + lane * 8 + 4) = ob;

    float ssd = da.x * da.x + da.y * da.y + da.z * da.z + da.w * da.w
              + db.x * db.x + db.y * db.y + db.z * db.z + db.w * db.w;
    #pragma unroll
    for (int off = 16; off > 0; off >>= 1) ssd += __shfl_xor_sync(0xffffffffu, ssd, off);
    if (lane == 0) warpsum[w] = (double)ssd;
    __syncthreads();
    if (threadIdx.x == 0) {
        double s = 0.0;
        #pragma unroll
        for (int q = 0; q < 8; q++) s += warpsum[q];
        atomicAdd(&g_ssd, s);
    }
}

__global__ void finalize_kernel(float* __restrict__ out, int out_size) {
    __shared__ double red[1024];
    int t = threadIdx.x;
    float p = (float)g_counts[t] * (1.0f / (float)NROWS);
    red[t] = (double)(p * logf(p + 1e-10f));
    __syncthreads();
    for (int s = 512; s > 0; s >>= 1) {
        if (t < s) red[t] += red[t + s];
        __syncthreads();
    }
    if (t == 0) {
        float perp = expf(-(float)red[0]);
        float loss = (float)(g_ssd * (1.25 / (double)QELEMS));
        out[out_size - 2] = loss;
        out[out_size - 1] = perp;
    }
}

extern "C" void kernel_launch(void* const* d_in, const int* in_sizes, int n_in,
                              void* d_out, int out_size) {
    const float* x  = (const float*)d_in[0];
    const float* cb = (const float*)d_in[1];
    float* out = (float*)d_out;

    cudaFuncSetAttribute(gemm_screen_kernel,
                         cudaFuncAttributeMaxDynamicSharedMemorySize, S_TOTAL);

    codesq_zero_kernel<<<KCODES / 256, 256>>>(cb);
    rowsq_kernel<<<NROWS / 256, 256>>>(x);
    packA_kernel<<<QELEMS / 8 / 256, 256>>>(x);
    packB_kernel<<<KCODES * DIM / 4 / 256, 256>>>(cb);
    gemm_screen_kernel<<<NROWS / 128, 256, S_TOTAL>>>();
    refine_gather_kernel<<<NROWS / 8, 256>>>(x, cb, out);
    finalize_kernel<<<1, 1024>>>(out, out_size);
}

// round 11
// speedup vs baseline: 1.7649x; 1.7649x over previous
#include <cuda_runtime.h>
#include <cstdint>

#define NROWS  32768
#define KCODES 1024
#define DIM    256
#define QELEMS (NROWS * DIM)
#define MARGIN 2.0e-3f
#define CAP    32

// Screen smem layout (bytes): B double buffers only (A goes gmem->regs)
#define S_B0    0
#define S_B1    16384
#define S_SE    32768       // 1024 floats
#define S_RMIN  36864       // 128 u32
#define S_CCNT  37376       // 128 int
#define S_CIDX  37888       // 128*32 int = 16KB
#define S_TOTAL 54272

// ---- scratch (static device globals) ----
__device__ int      g_idx[NROWS];
__device__ float    g_se[KCODES];
__device__ float    g_szi[NROWS];
__device__ int      g_counts[KCODES];
__device__ double   g_ssd;
__device__ uint32_t g_af[QELEMS];            // tf32-packed A fragments (32MB)
__device__ uint32_t g_bf[KCODES * DIM];      // tf32-packed B fragments (1MB)
__device__ int      g_ccnt[NROWS];
__device__ int      g_cidx[(size_t)NROWS * CAP];

__device__ __forceinline__ uint32_t smem_u32(const void* p) {
    uint32_t a;
    asm("{ .reg .u64 t; cvta.to.shared.u64 t, %1; cvt.u32.u64 %0, t; }"
        : "=r"(a) : "l"(p));
    return a;
}
__device__ __forceinline__ uint32_t to_tf32(float f) {
    uint32_t r;
    asm("cvt.rna.tf32.f32 %0, %1;" : "=r"(r) : "f"(f));
    return r;
}
__device__ __forceinline__ void cp16(uint32_t s, const void* g) {
    asm volatile("cp.async.cg.shared.global [%0], [%1], 16;" :: "r"(s), "l"(g));
}
#define CP_COMMIT() asm volatile("cp.async.commit_group;" ::: "memory")
#define CP_WAIT1()  asm volatile("cp.async.wait_group 1;" ::: "memory")
#define CP_WAIT0()  asm volatile("cp.async.wait_group 0;" ::: "memory")

// tf32 m16n8k8 MMA, fp32 accum (fragment maps validated R6/R7)
__device__ __forceinline__ void mma_tf32(float* c, const uint4& a, const uint2& b) {
    asm volatile(
        "mma.sync.aligned.m16n8k8.row.col.f32.tf32.tf32.f32 "
        "{%0,%1,%2,%3}, {%4,%5,%6,%7}, {%8,%9}, {%0,%1,%2,%3};"
        : "+f"(c[0]), "+f"(c[1]), "+f"(c[2]), "+f"(c[3])
        : "r"(a.x), "r"(a.y), "r"(a.z), "r"(a.w), "r"(b.x), "r"(b.y));
}

// ---- reference-exact sequential fp32 sumsq (DO NOT CHANGE ORDER) ----
__global__ void rowsq_kernel(const float* __restrict__ x) {
    int row = blockIdx.x * blockDim.x + threadIdx.x;
    if (row >= NROWS) return;
    const float4* p = reinterpret_cast<const float4*>(x) + (size_t)row * (DIM / 4);
    float s = 0.0f;
    #pragma unroll 4
    for (int i = 0; i < DIM / 4; i++) {
        float4 v = __ldg(p + i);
        s = __fadd_rn(s, __fmul_rn(v.x, v.x));
        s = __fadd_rn(s, __fmul_rn(v.y, v.y));
        s = __fadd_rn(s, __fmul_rn(v.z, v.z));
        s = __fadd_rn(s, __fmul_rn(v.w, v.w));
    }
    g_szi[row] = s;
}
__global__ void codesq_zero_kernel(const float* __restrict__ cb) {
    int code = blockIdx.x * blockDim.x + threadIdx.x;
    g_counts[code] = 0;
    if (code == 0) g_ssd = 0.0;
    const float4* p = reinterpret_cast<const float4*>(cb) + (size_t)code * (DIM / 4);
    float s = 0.0f;
    #pragma unroll 4
    for (int i = 0; i < DIM / 4; i++) {
        float4 v = __ldg(p + i);
        s = __fadd_rn(s, __fmul_rn(v.x, v.x));
        s = __fadd_rn(s, __fmul_rn(v.y, v.y));
        s = __fadd_rn(s, __fmul_rn(v.z, v.z));
        s = __fadd_rn(s, __fmul_rn(v.w, v.w));
    }
    g_se[code] = s;
}

// ---- pack A tf32 fragments: [mb(256)][ks(32)][mt(8)][lane(32)] uint4 ----
// a0:(r,c) a1:(r+8,c) a2:(r,c+4) a3:(r+8,c+4); r=lane>>2, c=lane&3
__global__ void packA_kernel(const float* __restrict__ x) {
    int t = blockIdx.x * 256 + threadIdx.x;      // 0 .. 2^21-1 uint4s
    int lane = t & 31, mt = (t >> 5) & 7, ks = (t >> 8) & 31, mb = t >> 13;
    int row = mb * 128 + mt * 16 + (lane >> 2);
    int d = ks * 8 + (lane & 3);
    const float* xr = x + (size_t)row * DIM + d;
    uint4 o;
    o.x = to_tf32(xr[0]);
    o.y = to_tf32(xr[8 * DIM]);
    o.z = to_tf32(xr[4]);
    o.w = to_tf32(xr[8 * DIM + 4]);
    reinterpret_cast<uint4*>(g_af)[t] = o;
}
// ---- pack B tf32 fragments: [nb(8)][ks(32)][nt(16)][lane(32)] uint2 ----
// b0:(k=lane&3+ks*8, n) b1:(k+4, n); n=nt*8+(lane>>2)
__global__ void packB_kernel(const float* __restrict__ cb) {
    int t = blockIdx.x * 256 + threadIdx.x;      // 0 .. 131071 uint2s
    int lane = t & 31, nt = (t >> 5) & 15, ks = (t >> 9) & 31, nb = t >> 14;
    int c = nb * 128 + nt * 8 + (lane >> 2);
    int d = ks * 8 + (lane & 3);
    uint2 o;
    o.x = to_tf32(cb[(size_t)c * DIM + d]);
    o.y = to_tf32(cb[(size_t)c * DIM + d + 4]);
    reinterpret_cast<uint2*>(g_bf)[t] = o;
}

// ---- tf32 screening GEMM + fused candidate selection ----
// A operands: direct LDG.128 from L2-resident fragment array (no smem staging).
// B operands: cp.async double-buffered smem.
__global__ __launch_bounds__(256, 2)
void gemm_screen_kernel() {
    extern __shared__ char sm[];
    const uint32_t sb = smem_u32(sm);
    const int tid = threadIdx.x;
    const int w = tid >> 5, lane = tid & 31;
    const int wm = w & 3, wn = w >> 2;        // 4 M-subtiles x 2 N-subtiles
    const int g = lane >> 2, tig = lane & 3;
    const int rowBase = blockIdx.x * 128;

    float* se_sm = reinterpret_cast<float*>(sm + S_SE);
    uint32_t* rmin = reinterpret_cast<uint32_t*>(sm + S_RMIN);
    int* ccnt = reinterpret_cast<int*>(sm + S_CCNT);
    int* cidx = reinterpret_cast<int*>(sm + S_CIDX);

    #pragma unroll
    for (int i = 0; i < 4; i++) se_sm[i * 256 + tid] = g_se[i * 256 + tid];
    if (tid < 128) { rmin[tid] = 0x7F800000u; ccnt[tid] = 0; }

    float szi[4];
    #pragma unroll
    for (int mt_i = 0; mt_i < 2; mt_i++)
        #pragma unroll
        for (int h = 0; h < 2; h++)
            szi[mt_i * 2 + h] = g_szi[rowBase + wm * 32 + mt_i * 16 + h * 8 + g];
    __syncthreads();

    const uint4* af4 = reinterpret_cast<const uint4*>(g_af);

    float C[2][8][4];

    {   // stage B chunk s=0 (16KB contiguous)
        const char* bsrc = reinterpret_cast<const char*>(g_bf);
        #pragma unroll
        for (int i = 0; i < 4; i++) {
            int idx = i * 256 + tid;
            cp16(sb + S_B0 + idx * 16, bsrc + idx * 16);
        }
        CP_COMMIT();
    }

    #pragma unroll 1
    for (int s = 0; s < 64; s++) {
        const int nb = s >> 3, kc = s & 7, buf = s & 1;

        if (s < 63) {
            const char* bsrc = reinterpret_cast<const char*>(g_bf) + (size_t)(s + 1) * 16384;
            uint32_t bbase = sb + ((s + 1) & 1 ? S_B1 : S_B0);
            #pragma unroll
            for (int i = 0; i < 4; i++) {
                int idx = i * 256 + tid;
                cp16(bbase + idx * 16, bsrc + idx * 16);
            }
            CP_COMMIT();
            CP_WAIT1();
        } else {
            CP_WAIT0();
        }
        __syncthreads();

        if (kc == 0) {
            #pragma unroll
            for (int m = 0; m < 2; m++)
                #pragma unroll
                for (int j = 0; j < 8; j++)
                    #pragma unroll
                    for (int q = 0; q < 4; q++) C[m][j][q] = 0.0f;
        }

        const char* Bb = sm + (buf ? S_B1 : S_B0);
        #pragma unroll
        for (int ksl = 0; ksl < 4; ksl++) {
            int ksg = kc * 4 + ksl;
            // A fragments direct from gmem (L2-resident), coalesced per warp
            uint4 A0 = __ldg(af4 + ((size_t)(blockIdx.x * 32 + ksg) * 8 + wm * 2 + 0) * 32 + lane);
            uint4 A1 = __ldg(af4 + ((size_t)(blockIdx.x * 32 + ksg) * 8 + wm * 2 + 1) * 32 + lane);
            #pragma unroll
            for (int j = 0; j < 8; j++) {
                uint2 b = *reinterpret_cast<const uint2*>(
                    Bb + ((ksl * 16 + wn * 8 + j) * 32 + lane) * 8);
                mma_tf32(C[0][j], A0, b);
                mma_tf32(C[1][j], A1, b);
            }
        }
        __syncthreads();

        if (kc == 7) {
            // epilogue: candidate = d <= min(cached_row_min, local_min) + MARGIN
            #pragma unroll
            for (int mt_i = 0; mt_i < 2; mt_i++) {
                int rl0 = wm * 32 + mt_i * 16 + g;
                int rl1 = rl0 + 8;
                float s0 = szi[mt_i * 2], s1 = szi[mt_i * 2 + 1];
                float d0v[16], d1v[16];
                float lm0 = 3.0e38f, lm1 = 3.0e38f;
                #pragma unroll
                for (int j = 0; j < 8; j++) {
                    int colb = nb * 128 + wn * 64 + j * 8 + tig * 2;
                    float se0 = se_sm[colb], se1 = se_sm[colb + 1];
                    d0v[j * 2]     = fmaf(-2.0f, C[mt_i][j][0], s0 + se0);
                    d0v[j * 2 + 1] = fmaf(-2.0f, C[mt_i][j][1], s0 + se1);
                    d1v[j * 2]     = fmaf(-2.0f, C[mt_i][j][2], s1 + se0);
                    d1v[j * 2 + 1] = fmaf(-2.0f, C[mt_i][j][3], s1 + se1);
                    lm0 = fminf(lm0, fminf(d0v[j * 2], d0v[j * 2 + 1]));
                    lm1 = fminf(lm1, fminf(d1v[j * 2], d1v[j * 2 + 1]));
                }
                float cm0 = fminf(__uint_as_float(rmin[rl0]), lm0);
                float cm1 = fminf(__uint_as_float(rmin[rl1]), lm1);
                atomicMin(&rmin[rl0], __float_as_uint(lm0));
                atomicMin(&rmin[rl1], __float_as_uint(lm1));
                float t0 = cm0 + MARGIN, t1 = cm1 + MARGIN;
                #pragma unroll
                for (int q = 0; q < 16; q++) {
                    int code = nb * 128 + wn * 64 + (q >> 1) * 8 + tig * 2 + (q & 1);
                    if (d0v[q] <= t0) {
                        int p = atomicAdd(&ccnt[rl0], 1);
                        if (p < CAP) cidx[rl0 * CAP + p] = code;
                    }
                    if (d1v[q] <= t1) {
                        int p = atomicAdd(&ccnt[rl1], 1);
                        if (p < CAP) cidx[rl1 * CAP + p] = code;
                    }
                }
            }
        }
    }

    __syncthreads();
    if (tid < 128) g_ccnt[rowBase + tid] = ccnt[tid];
    #pragma unroll
    for (int i = 0; i < 16; i++) {
        int li = i * 256 + tid;                 // 0..4095
        int r = li >> 5, k = li & 31;
        if (k < ccnt[r])
            g_cidx[(size_t)(rowBase + r) * CAP + k] = cidx[r * CAP + k];
    }
}

// ---- fused refine (exact argmin over candidates) + gather/output/ssd/hist ----
__global__ void refine_gather_kernel(const float* __restrict__ x,
                                     const float* __restrict__ cb,
                                     float* __restrict__ out) {
    __shared__ double warpsum[8];
    int w = threadIdx.x >> 5, lane = threadIdx.x & 31;
    int row = blockIdx.x * 8 + w;

    float4 xa = *reinterpret_cast<const float4*>(x + (size_t)row * DIM + lane * 8);
    float4 xb = *reinterpret_cast<const float4*>(x + (size_t)row * DIM + lane * 8 + 4);
    float szi = g_szi[row];
    int cnt = g_ccnt[row];

    float bd = 3.0e38f;
    int bi = 0x7FFFFFFF;
    if (cnt <= CAP) {
        for (int k = 0; k < cnt; k++) {
            int c = g_cidx[(size_t)row * CAP + k];
            float4 ea = *reinterpret_cast<const float4*>(cb + (size_t)c * DIM + lane * 8);
            float4 eb = *reinterpret_cast<const float4*>(cb + (size_t)c * DIM + lane * 8 + 4);
            float p = xa.x * ea.x;
            p = fmaf(xa.y, ea.y, p); p = fmaf(xa.z, ea.z, p); p = fmaf(xa.w, ea.w, p);
            p = fmaf(xb.x, eb.x, p); p = fmaf(xb.y, eb.y, p);
            p = fmaf(xb.z, eb.z, p); p = fmaf(xb.w, eb.w, p);
            #pragma unroll
            for (int off = 16; off > 0; off >>= 1) p += __shfl_xor_sync(0xffffffffu, p, off);
            // reference-exact epilogue: dist = fl(fl(szi+se) - fl(2*dot))
            float dist = __fsub_rn(__fadd_rn(szi, g_se[c]), __fmul_rn(2.0f, p));
            if (dist < bd || (dist == bd && c < bi)) { bd = dist; bi = c; }
        }
    } else {
        // overflow fallback: exact scan of all codes (expected never)
        for (int c = 0; c < KCODES; c++) {
            float4 ea = *reinterpret_cast<const float4*>(cb + (size_t)c * DIM + lane * 8);
            float4 eb = *reinterpret_cast<const float4*>(cb + (size_t)c * DIM + lane * 8 + 4);
            float p = xa.x * ea.x;
            p = fmaf(xa.y, ea.y, p); p = fmaf(xa.z, ea.z, p); p = fmaf(xa.w, ea.w, p);
            p = fmaf(xb.x, eb.x, p); p = fmaf(xb.y, eb.y, p);
            p = fmaf(xb.z, eb.z, p); p = fmaf(xb.w, eb.w, p);
            #pragma unroll
            for (int off = 16; off > 0; off >>= 1) p += __shfl_xor_sync(0xffffffffu, p, off);
            float dist = __fsub_rn(__fadd_rn(szi, g_se[c]), __fmul_rn(2.0f, p));
            if (dist < bd) { bd = dist; bi = c; }   // ascending: '<' keeps lowest
        }
    }

    if (lane == 0) { g_idx[row] = bi; atomicAdd(&g_counts[bi], 1); }

    // gather + straight-through output + ssd (reference rounding: o = x + (q-x))
    float4 qa = *reinterpret_cast<const float4*>(cb + (size_t)bi * DIM + lane * 8);
    float4 qb = *reinterpret_cast<const float4*>(cb + (size_t)bi * DIM + lane * 8 + 4);
    float4 da, db, oa, ob;
    da.x = __fsub_rn(qa.x, xa.x); da.y = __fsub_rn(qa.y, xa.y);
    da.z = __fsub_rn(qa.z, xa.z); da.w = __fsub_rn(qa.w, xa.w);
    db.x = __fsub_rn(qb.x, xb.x); db.y = __fsub_rn(qb.y, xb.y);
    db.z = __fsub_rn(qb.z, xb.z); db.w = __fsub_rn(qb.w, xb.w);
    oa.x = __fadd_rn(xa.x, da.x); oa.y = __fadd_rn(xa.y, da.y);
    oa.z = __fadd_rn(xa.z, da.z); oa.w = __fadd_rn(xa.w, da.w);
    ob.x = __fadd_rn(xb.x, db.x); ob.y = __fadd_rn(xb.y, db.y);
    ob.z = __fadd_rn(xb.z, db.z); ob.w = __fadd_rn(xb.w, db.w);
    *reinterpret_cast<float4*>(out + (size_t)row * DIM + lane * 8)     = oa;
    *reinterpret_cast<float4*>(out + (size_t)row * DIM + lane * 8 + 4) = ob;

    float ssd = da.x * da.x + da.y * da.y + da.z * da.z + da.w * da.w
              + db.x * db.x + db.y * db.y + db.z * db.z + db.w * db.w;
    #pragma unroll
    for (int off = 16; off > 0; off >>= 1) ssd += __shfl_xor_sync(0xffffffffu, ssd, off);
    if (lane == 0) warpsum[w] = (double)ssd;
    __syncthreads();
    if (threadIdx.x == 0) {
        double s = 0.0;
        #pragma unroll
        for (int q = 0; q < 8; q++) s += warpsum[q];
        atomicAdd(&g_ssd, s);
    }
}

__global__ void finalize_kernel(float* __restrict__ out, int out_size) {
    __shared__ double red[1024];
    int t = threadIdx.x;
    float p = (float)g_counts[t] * (1.0f / (float)NROWS);
    red[t] = (double)(p * logf(p + 1e-10f));
    __syncthreads();
    for (int s = 512; s > 0; s >>= 1) {
        if (t < s) red[t] += red[t + s];
        __syncthreads();
    }
    if (t == 0) {
        float perp = expf(-(float)red[0]);
        float loss = (float)(g_ssd * (1.25 / (double)QELEMS));
        out[out_size - 2] = loss;
        out[out_size - 1] = perp;
    }
}

extern "C" void kernel_launch(void* const* d_in, const int* in_sizes, int n_in,
                              void* d_out, int out_size) {
    const float* x  = (const float*)d_in[0];
    const float* cb = (const float*)d_in[1];
    float* out = (float*)d_out;

    cudaFuncSetAttribute(gemm_screen_kernel,
                         cudaFuncAttributeMaxDynamicSharedMemorySize, S_TOTAL);

    codesq_zero_kernel<<<KCODES / 256, 256>>>(cb);
    rowsq_kernel<<<NROWS / 256, 256>>>(x);
    packA_kernel<<<QELEMS / 4 / 256, 256>>>(x);
    packB_kernel<<<KCODES * DIM / 2 / 256, 256>>>(cb);
    gemm_screen_kernel<<<NROWS / 128, 256, S_TOTAL>>>();
    refine_gather_kernel<<<NROWS / 8, 256>>>(x, cb, out);
    finalize_kernel<<<1, 1024>>>(out, out_size);
}